// round 2
// baseline (speedup 1.0000x reference)
#include <cuda_runtime.h>
#include <math.h>

// ----------------------------------------------------------------------------
// MemoryNetwork fused kernel, GB300 sm_103a
//
// Reference math collapses:
//   M1[d,m,:] = W_topic  @ mems_d[d,m]   (2048-dim)
//   M2[d,m,:] = W_domain @ mems_d[d,m]
//   s_b = TAU / max(||feature_b||, eps)
//   P1[b,r] = feature_b . M1[r],  P2[b,r] = feature_b . M2[r]   (r = d*10+m)
//   topic_att = softmax_m(s_b * P1[b,d,:])
//   L[b,d]    = s_b * sum_m topic_att * P2[b,d,m]
//   out[b,d]  = softmax_d(L[b,:])
//
// Kernel A: build M (192x2048 scratch; rows 0..95 topic (90 real), 96..191 domain)
// Kernel B: tiled fp32 GEMM (16384x2048)@(2048x192) with f32x2 packed FMA,
//           fused row-norm + double softmax epilogue.
// ----------------------------------------------------------------------------

#define B_TOTAL 16384
#define K_DIM   2048
#define EMB     768
#define TAUF    32.0f

#define BM 128
#define BN 192
#define BK 32
#define CS_LD 193   // padded stride for C smem (conflict-free column reads)

__device__ float g_M[192 * 2048];  // 1.5 MB scratch

// ---- packed f32x2 helpers --------------------------------------------------
__device__ __forceinline__ unsigned long long dup2(float x) {
    unsigned long long r;
    asm("mov.b64 %0, {%1, %1};" : "=l"(r) : "f"(x));
    return r;
}
__device__ __forceinline__ void ffma2(unsigned long long& d,
                                      unsigned long long a,
                                      unsigned long long b) {
    asm("fma.rn.f32x2 %0, %1, %2, %0;" : "+l"(d) : "l"(a), "l"(b));
}
__device__ __forceinline__ float2 unpack2(unsigned long long v) {
    float2 f;
    asm("mov.b64 {%0, %1}, %2;" : "=f"(f.x), "=f"(f.y) : "l"(v));
    return f;
}

// ----------------------------------------------------------------------------
// Kernel A: M[row][k] = sum_e mem[row][e] * W[e][k]
// grid: (8 kchunks, 16 rowgroups of 12), 256 threads (one k column each)
// ----------------------------------------------------------------------------
__global__ void __launch_bounds__(256) build_M_kernel(
    const float* __restrict__ Wt,
    const float* __restrict__ Wd,
    const float* __restrict__ memtab,
    const void*  __restrict__ catp)
{
    __shared__ float memsm[EMB][12];   // [e][rr], 16B-aligned rows (48 bytes)

    const int tid = threadIdx.x;
    const int kc  = blockIdx.x;        // 0..7
    const int ry  = blockIdx.y;        // 0..15
    const int mtx = ry >> 3;           // 0 = topic, 1 = domain
    const int grp = ry & 7;            // rowgroup within matrix
    const int k   = kc * 256 + tid;

    // category may arrive as int32 or int64; detect from high words of first 9
    const int* c32 = (const int*)catp;
    bool is64 = true;
    #pragma unroll
    for (int j = 0; j < 9; j++) if (c32[2 * j + 1] != 0) is64 = false;
    int catv[9];
    #pragma unroll
    for (int j = 0; j < 9; j++)
        catv[j] = is64 ? (int)(((const long long*)catp)[j]) : c32[j];

    // cooperative load of 12 memory rows (zeros for padding rows)
    for (int idx = tid; idx < 12 * EMB; idx += 256) {
        int rr = idx / EMB;
        int e  = idx % EMB;
        int gr = grp * 12 + rr;        // row within this matrix, 0..95
        float v = 0.0f;
        if (gr < 90) {
            int d = gr / 10, m = gr % 10;
            v = memtab[(catv[d] * 10 + m) * EMB + e];
        }
        memsm[e][rr] = v;
    }
    __syncthreads();

    const float* W = mtx ? Wd : Wt;

    unsigned long long acc[6];
    #pragma unroll
    for (int j = 0; j < 6; j++) acc[j] = 0ull;

    #pragma unroll 4
    for (int e = 0; e < EMB; e++) {
        unsigned long long wd = dup2(W[e * K_DIM + k]);
        const ulonglong2* mr = (const ulonglong2*)(&memsm[e][0]);
        ulonglong2 p0 = mr[0], p1 = mr[1], p2 = mr[2];
        ffma2(acc[0], p0.x, wd);
        ffma2(acc[1], p0.y, wd);
        ffma2(acc[2], p1.x, wd);
        ffma2(acc[3], p1.y, wd);
        ffma2(acc[4], p2.x, wd);
        ffma2(acc[5], p2.y, wd);
    }

    const int base_row = mtx * 96 + grp * 12;
    #pragma unroll
    for (int j = 0; j < 6; j++) {
        float2 v = unpack2(acc[j]);
        g_M[(base_row + 2 * j)     * K_DIM + k] = v.x;
        g_M[(base_row + 2 * j + 1) * K_DIM + k] = v.y;
    }
}

// ----------------------------------------------------------------------------
// Kernel B: fused GEMM + norms + softmaxes
// grid 128 blocks (BM=128 rows each), 256 threads (16x16), TM=8, TN=12 (f32x2: 6 pairs)
// dyn smem: phase1 As2[32][256] (A dup-paired) + Bs[32][192]; phase2 Cs[128][193]+rowsum
// ----------------------------------------------------------------------------
__global__ void __launch_bounds__(256, 1) fused_kernel(
    const float* __restrict__ feat,
    float*       __restrict__ out)
{
    extern __shared__ float smem[];
    float* As2    = smem;                  // 32*256 floats (A values duplicated in pairs)
    float* Bs     = smem + 32 * 256;       // 32*192 floats
    float* Cs     = smem;                  // 128*193 floats (reuses As2/Bs region)
    float* rowsum = smem + 128 * CS_LD;    // 128 floats (outside Cs)

    const int tid = threadIdx.x;
    const int tx  = tid & 15;
    const int ty  = tid >> 4;
    const int b0  = blockIdx.x * BM;

    unsigned long long acc[8][6];
    #pragma unroll
    for (int i = 0; i < 8; i++)
        #pragma unroll
        for (int j = 0; j < 6; j++) acc[i][j] = 0ull;

    float4 aregs[4];
    float4 bregs[6];
    float  ss[4] = {0.f, 0.f, 0.f, 0.f};

    // ---- tile loaders (register prefetch) ----
    auto loadA = [&](int k0) {
        #pragma unroll
        for (int l = 0; l < 4; l++) {
            int f = tid + 256 * l, r = f >> 3, c4 = f & 7;
            aregs[l] = *(const float4*)(feat + (b0 + r) * K_DIM + k0 + c4 * 4);
        }
    };
    auto loadB = [&](int k0) {
        #pragma unroll
        for (int l = 0; l < 6; l++) {
            int f = tid + 256 * l, n = f >> 3, c4 = f & 7;
            bregs[l] = *(const float4*)(g_M + n * K_DIM + k0 + c4 * 4);
        }
    };
    auto stsTiles = [&]() {
        #pragma unroll
        for (int l = 0; l < 4; l++) {
            int f = tid + 256 * l, r = f >> 3, c4 = f & 7;
            float4 v = aregs[l];
            ((float2*)(As2 + (c4 * 4 + 0) * 256))[r] = make_float2(v.x, v.x);
            ((float2*)(As2 + (c4 * 4 + 1) * 256))[r] = make_float2(v.y, v.y);
            ((float2*)(As2 + (c4 * 4 + 2) * 256))[r] = make_float2(v.z, v.z);
            ((float2*)(As2 + (c4 * 4 + 3) * 256))[r] = make_float2(v.w, v.w);
            ss[l] += v.x * v.x + v.y * v.y + v.z * v.z + v.w * v.w;
        }
        #pragma unroll
        for (int l = 0; l < 6; l++) {
            int f = tid + 256 * l, n = f >> 3, c4 = f & 7;
            float4 v = bregs[l];
            Bs[(c4 * 4 + 0) * BN + n] = v.x;
            Bs[(c4 * 4 + 1) * BN + n] = v.y;
            Bs[(c4 * 4 + 2) * BN + n] = v.z;
            Bs[(c4 * 4 + 3) * BN + n] = v.w;
        }
    };

    loadA(0);
    loadB(0);

    const int NIT = K_DIM / BK;  // 64
    for (int it = 0; it < NIT; it++) {
        stsTiles();
        __syncthreads();
        if (it + 1 < NIT) {             // prefetch next tile under compute
            loadA((it + 1) * BK);
            loadB((it + 1) * BK);
        }
        #pragma unroll 8
        for (int kk = 0; kk < BK; kk++) {
            const ulonglong2* ap = (const ulonglong2*)(As2 + kk * 256 + ty * 16);
            ulonglong2 a01 = ap[0], a23 = ap[1], a45 = ap[2], a67 = ap[3];
            const ulonglong2* bp = (const ulonglong2*)(Bs + kk * BN + tx * 12);
            ulonglong2 bA = bp[0], bB = bp[1], bC = bp[2];
            unsigned long long av[8] = {a01.x, a01.y, a23.x, a23.y,
                                        a45.x, a45.y, a67.x, a67.y};
            unsigned long long bv[6] = {bA.x, bA.y, bB.x, bB.y, bC.x, bC.y};
            #pragma unroll
            for (int i = 0; i < 8; i++)
                #pragma unroll
                for (int j = 0; j < 6; j++)
                    ffma2(acc[i][j], av[i], bv[j]);
        }
        __syncthreads();
    }

    // ---- epilogue: stash C + row sums in smem ----
    if (tid < 128) rowsum[tid] = 0.0f;
    __syncthreads();
    #pragma unroll
    for (int l = 0; l < 4; l++)
        atomicAdd(&rowsum[(tid >> 3) + 32 * l], ss[l]);

    #pragma unroll
    for (int i = 0; i < 8; i++) {
        int row = ty * 8 + i;
        #pragma unroll
        for (int j = 0; j < 6; j++) {
            float2 v = unpack2(acc[i][j]);
            Cs[row * CS_LD + tx * 12 + 2 * j]     = v.x;
            Cs[row * CS_LD + tx * 12 + 2 * j + 1] = v.y;
        }
    }
    __syncthreads();

    // ---- per-row softmax chain (threads 0..127, one row each) ----
    if (tid < 128) {
        const int   row = tid;
        const int   b   = b0 + row;
        const float s   = TAUF / fmaxf(sqrtf(rowsum[row]), 1e-12f);
        const float* cr = Cs + row * CS_LD;

        float L[9];
        #pragma unroll
        for (int d = 0; d < 9; d++) {
            float mx = -1e30f;
            #pragma unroll
            for (int m = 0; m < 10; m++) mx = fmaxf(mx, cr[d * 10 + m]);
            float se = 0.f, ac = 0.f;
            #pragma unroll
            for (int m = 0; m < 10; m++) {
                float e = expf(s * (cr[d * 10 + m] - mx));
                se += e;
                ac += e * cr[96 + d * 10 + m];
            }
            L[d] = s * ac / se;
        }
        float mx2 = -1e30f;
        #pragma unroll
        for (int d = 0; d < 9; d++) mx2 = fmaxf(mx2, L[d]);
        float ex[9], s2 = 0.f;
        #pragma unroll
        for (int d = 0; d < 9; d++) { ex[d] = expf(L[d] - mx2); s2 += ex[d]; }
        const float inv = 1.0f / s2;
        #pragma unroll
        for (int d = 0; d < 9; d++) out[b * 9 + d] = ex[d] * inv;
    }
}

// ----------------------------------------------------------------------------
extern "C" void kernel_launch(void* const* d_in, const int* in_sizes, int n_in,
                              void* d_out, int out_size)
{
    const float* feature = (const float*)d_in[0];  // (16384, 2048)
    const float* Wt      = (const float*)d_in[1];  // (768, 2048)
    const float* Wd      = (const float*)d_in[2];  // (768, 2048)
    const float* memtab  = (const float*)d_in[3];  // (9, 10, 768)
    const void*  cat     = d_in[4];                // (16384,) int32 or int64

    const int dyn_smem = (128 * CS_LD + 128) * (int)sizeof(float);  // 99328
    cudaFuncSetAttribute(fused_kernel,
                         cudaFuncAttributeMaxDynamicSharedMemorySize, dyn_smem);

    dim3 gA(8, 16);
    build_M_kernel<<<gA, 256>>>(Wt, Wd, memtab, cat);
    fused_kernel<<<B_TOTAL / BM, 256, dyn_smem>>>(feature, (float*)d_out);
}

// round 4
// speedup vs baseline: 3.0142x; 3.0142x over previous
#include <cuda_runtime.h>
#include <cuda_bf16.h>
#include <math.h>
#include <stdint.h>

// ----------------------------------------------------------------------------
// MemoryNetwork, GB300 sm_103a (PTX target sm_103 => family-portable ISA only)
//
//   M1[d,m,:] = W_topic  @ mems_d[d,m]; M2 likewise (rows 0..95 topic, 96..191 domain)
//   P[b,r]    = feature_b . M[r]   via mma.sync bf16 hi/lo split (3 passes, fp32 acc)
//   fused row-norm + topic softmax + domain softmax epilogue.
// ----------------------------------------------------------------------------

#define K_DIM   2048
#define TAUF    32.0f
#define NROWS   192
#define KC      64            // bf16 K per chunk
#define NCH     (K_DIM / KC)  // 32

__device__ float                        g_part[4 * NROWS * K_DIM];
__device__ __align__(16) unsigned short g_Bh[NROWS * K_DIM];
__device__ __align__(16) unsigned short g_Bl[NROWS * K_DIM];

// ---------------- helpers ----------------
__device__ __forceinline__ uint32_t smem_u32(const void* p) {
    uint32_t a;
    asm("{ .reg .u64 t; cvta.to.shared.u64 t, %1; cvt.u32.u64 %0, t; }" : "=r"(a) : "l"(p));
    return a;
}
__device__ __forceinline__ unsigned long long dup2(float x) {
    unsigned long long r; asm("mov.b64 %0, {%1, %1};" : "=l"(r) : "f"(x)); return r;
}
__device__ __forceinline__ void ffma2(unsigned long long& d, unsigned long long a,
                                      unsigned long long b) {
    asm("fma.rn.f32x2 %0, %1, %2, %0;" : "+l"(d) : "l"(a), "l"(b));
}
__device__ __forceinline__ float2 unpack2(unsigned long long v) {
    float2 f; asm("mov.b64 {%0, %1}, %2;" : "=f"(f.x), "=f"(f.y) : "l"(v)); return f;
}
__device__ __forceinline__ uint32_t cvt_bf16x2(float lo, float hi) {
    uint32_t r; asm("cvt.rn.bf16x2.f32 %0, %1, %2;" : "=r"(r) : "f"(hi), "f"(lo)); return r;
}
__device__ __forceinline__ void ldsm4(uint32_t* r, uint32_t addr) {
    asm volatile("ldmatrix.sync.aligned.m8n8.x4.shared.b16 {%0,%1,%2,%3}, [%4];"
                 : "=r"(r[0]), "=r"(r[1]), "=r"(r[2]), "=r"(r[3]) : "r"(addr));
}
__device__ __forceinline__ void mma16816(float* d, const uint32_t* a, const uint32_t* b) {
    asm volatile("mma.sync.aligned.m16n8k16.row.col.f32.bf16.bf16.f32 "
                 "{%0,%1,%2,%3}, {%4,%5,%6,%7}, {%8,%9}, {%0,%1,%2,%3};"
                 : "+f"(d[0]), "+f"(d[1]), "+f"(d[2]), "+f"(d[3])
                 : "r"(a[0]), "r"(a[1]), "r"(a[2]), "r"(a[3]), "r"(b[0]), "r"(b[1]));
}

// ----------------------------------------------------------------------------
// A1: split-K partials  g_part[ec][row][k] = sum_{e in chunk} mem[row][e] * W[e][k]
// grid (8 kc, 16 rowgroup, 4 echunk), 256 threads
// ----------------------------------------------------------------------------
__global__ void __launch_bounds__(256) build_part_kernel(
    const float* __restrict__ Wt, const float* __restrict__ Wd,
    const float* __restrict__ memtab, const void* __restrict__ catp)
{
    __shared__ __align__(16) float memsm[192][12];

    const int tid = threadIdx.x;
    const int k   = blockIdx.x * 256 + tid;
    const int ry  = blockIdx.y;
    const int ec  = blockIdx.z;
    const int mtx = ry >> 3;
    const int grp = ry & 7;
    const int e0  = ec * 192;

    const int* c32 = (const int*)catp;
    bool is64 = true;
    #pragma unroll
    for (int j = 0; j < 9; j++) if (c32[2 * j + 1] != 0) is64 = false;
    int catv[9];
    #pragma unroll
    for (int j = 0; j < 9; j++)
        catv[j] = is64 ? (int)(((const long long*)catp)[j]) : c32[j];

    for (int idx = tid; idx < 12 * 192; idx += 256) {
        int rr = idx / 192, e = idx % 192;
        int gr = grp * 12 + rr;
        float v = 0.0f;
        if (gr < 90) {
            int d = gr / 10, m = gr % 10;
            v = memtab[(catv[d] * 10 + m) * 768 + e0 + e];
        }
        memsm[e][rr] = v;
    }
    __syncthreads();

    const float* W = mtx ? Wd : Wt;
    unsigned long long acc[6];
    #pragma unroll
    for (int j = 0; j < 6; j++) acc[j] = 0ull;

    #pragma unroll 8
    for (int e = 0; e < 192; e++) {
        unsigned long long wd = dup2(W[(size_t)(e0 + e) * K_DIM + k]);
        const ulonglong2* mr = (const ulonglong2*)(&memsm[e][0]);
        ulonglong2 p0 = mr[0], p1 = mr[1], p2 = mr[2];
        ffma2(acc[0], p0.x, wd); ffma2(acc[1], p0.y, wd);
        ffma2(acc[2], p1.x, wd); ffma2(acc[3], p1.y, wd);
        ffma2(acc[4], p2.x, wd); ffma2(acc[5], p2.y, wd);
    }

    const int base_row = mtx * 96 + grp * 12;
    float* dst = g_part + (size_t)ec * NROWS * K_DIM;
    #pragma unroll
    for (int j = 0; j < 6; j++) {
        float2 v = unpack2(acc[j]);
        dst[(base_row + 2 * j)     * K_DIM + k] = v.x;
        dst[(base_row + 2 * j + 1) * K_DIM + k] = v.y;
    }
}

// ----------------------------------------------------------------------------
// A2: reduce partials; split into bf16 hi (truncated) + lo (rounded)
// ----------------------------------------------------------------------------
__global__ void __launch_bounds__(256) split_B_kernel()
{
    const int row = blockIdx.x;
    #pragma unroll
    for (int i = 0; i < 8; i++) {
        int col = threadIdx.x + 256 * i;
        size_t off = (size_t)row * K_DIM + col;
        float s = g_part[off] + g_part[off + 1ull * NROWS * K_DIM]
                + g_part[off + 2ull * NROWS * K_DIM] + g_part[off + 3ull * NROWS * K_DIM];
        uint32_t u = __float_as_uint(s);
        float hif = __uint_as_float(u & 0xFFFF0000u);
        float lo  = s - hif;
        __nv_bfloat16 lb = __float2bfloat16(lo);
        g_Bh[off] = (unsigned short)(u >> 16);
        g_Bl[off] = *(unsigned short*)&lb;
    }
}

// ----------------------------------------------------------------------------
// Fused mma.sync GEMM + norms + softmaxes
// 128 CTAs x 256 threads (8 warps as 4x2); per-CTA tile M=128, N=192
// SMEM phase1: Ah/Al 128x72 bf16, Bh/Bl 192x72 bf16 (stride 72 = ldsm-conflict-free)
// SMEM phase2: Cs 128x194 f32 + rowsum
// ----------------------------------------------------------------------------
#define LDS_A   72
#define AH_OFF  0
#define AL_OFF  18432
#define BH_OFF  36864
#define BL_OFF  64512
#define CS_LD   194
#define RS_OFF  99328                       // 128*194*4
#define SMEM_TOT (RS_OFF + 128 * 4)         // 99840

__global__ void __launch_bounds__(256, 1) fused_kernel(
    const float* __restrict__ feat, float* __restrict__ out)
{
    extern __shared__ __align__(16) char smem[];
    const uint32_t sbase = smem_u32(smem);
    float* Cs     = (float*)smem;
    float* rowsum = (float*)(smem + RS_OFF);

    const int tid  = threadIdx.x;
    const int lane = tid & 31;
    const int wid  = tid >> 5;
    const int wr   = wid >> 1;      // 0..3 -> 32-row band
    const int wc   = wid & 1;       // 0..1 -> 96-col band
    const int b0   = blockIdx.x * 128;

    if (tid < 128) rowsum[tid] = 0.0f;
    __syncthreads();

    float acc[2][12][4];
    #pragma unroll
    for (int i = 0; i < 2; i++)
        #pragma unroll
        for (int j = 0; j < 12; j++)
            #pragma unroll
            for (int q = 0; q < 4; q++) acc[i][j][q] = 0.0f;

    float ss[4] = {0.f, 0.f, 0.f, 0.f};
    float4 aregs[8];

    auto loadA = [&](int kc) {
        #pragma unroll
        for (int l = 0; l < 4; l++) {
            int ci = tid + 256 * l, r = ci >> 3, cc = ci & 7;
            const float4* src = (const float4*)(feat + (size_t)(b0 + r) * K_DIM + kc + cc * 8);
            aregs[2 * l]     = src[0];
            aregs[2 * l + 1] = src[1];
        }
    };

    loadA(0);

    for (int c = 0; c < NCH; c++) {
        const int kc = c * KC;

        // ---- A: split hi/lo from prefetched regs, accumulate rowsum, STS ----
        #pragma unroll
        for (int l = 0; l < 4; l++) {
            int ci = tid + 256 * l, r = ci >> 3, cc = ci & 7;
            float4 v0 = aregs[2 * l], v1 = aregs[2 * l + 1];
            float f[8] = {v0.x, v0.y, v0.z, v0.w, v1.x, v1.y, v1.z, v1.w};
            ss[l] += f[0]*f[0] + f[1]*f[1] + f[2]*f[2] + f[3]*f[3]
                   + f[4]*f[4] + f[5]*f[5] + f[6]*f[6] + f[7]*f[7];
            uint32_t hi[4], lo[4];
            #pragma unroll
            for (int p = 0; p < 4; p++) {
                uint32_t u0 = __float_as_uint(f[2*p]), u1 = __float_as_uint(f[2*p+1]);
                hi[p] = (u0 >> 16) | (u1 & 0xFFFF0000u);
                float l0 = f[2*p]   - __uint_as_float(u0 & 0xFFFF0000u);
                float l1 = f[2*p+1] - __uint_as_float(u1 & 0xFFFF0000u);
                lo[p] = cvt_bf16x2(l0, l1);
            }
            uint32_t boff = (uint32_t)(r * (LDS_A * 2) + cc * 16);
            *(uint4*)(smem + AH_OFF + boff) = make_uint4(hi[0], hi[1], hi[2], hi[3]);
            *(uint4*)(smem + AL_OFF + boff) = make_uint4(lo[0], lo[1], lo[2], lo[3]);
        }
        // ---- B: direct from L2-resident globals, STS ----
        #pragma unroll
        for (int l = 0; l < 6; l++) {
            int ci = tid + 256 * l, r = ci >> 3, cc = ci & 7;
            size_t g = (size_t)r * K_DIM + kc + cc * 8;
            uint4 vh = *(const uint4*)(g_Bh + g);
            uint4 vl = *(const uint4*)(g_Bl + g);
            uint32_t boff = (uint32_t)(r * (LDS_A * 2) + cc * 16);
            *(uint4*)(smem + BH_OFF + boff) = vh;
            *(uint4*)(smem + BL_OFF + boff) = vl;
        }
        __syncthreads();

        if (c + 1 < NCH) loadA(kc + KC);   // LDGs in flight under the mma block

        // ---- warp mma: 3 split passes over this 64-wide K chunk ----
        const int mbase = wr * 32;
        const int nbase = wc * 96;
        #pragma unroll
        for (int k16 = 0; k16 < 4; k16++) {
            const uint32_t akoff = (uint32_t)(k16 * 16 + (lane >> 4) * 8) * 2;
            const uint32_t bkoff = (uint32_t)(k16 * 16 + ((lane >> 3) & 1) * 8) * 2;

            uint32_t ah[2][4], al[2][4];
            #pragma unroll
            for (int mt = 0; mt < 2; mt++) {
                uint32_t rowb = (uint32_t)(mbase + mt * 16 + (lane & 15)) * (LDS_A * 2);
                ldsm4(ah[mt], sbase + AH_OFF + rowb + akoff);
                ldsm4(al[mt], sbase + AL_OFF + rowb + akoff);
            }
            uint32_t bh[6][4];
            #pragma unroll
            for (int bt = 0; bt < 6; bt++) {
                uint32_t rowb = (uint32_t)(nbase + bt * 16 + (lane & 7) + ((lane >> 4) << 3))
                              * (LDS_A * 2);
                ldsm4(bh[bt], sbase + BH_OFF + rowb + bkoff);
            }
            #pragma unroll
            for (int mt = 0; mt < 2; mt++)
                #pragma unroll
                for (int nt = 0; nt < 12; nt++) {
                    mma16816(acc[mt][nt], ah[mt], &bh[nt >> 1][(nt & 1) * 2]);
                    mma16816(acc[mt][nt], al[mt], &bh[nt >> 1][(nt & 1) * 2]);
                }
            uint32_t bl[6][4];
            #pragma unroll
            for (int bt = 0; bt < 6; bt++) {
                uint32_t rowb = (uint32_t)(nbase + bt * 16 + (lane & 7) + ((lane >> 4) << 3))
                              * (LDS_A * 2);
                ldsm4(bl[bt], sbase + BL_OFF + rowb + bkoff);
            }
            #pragma unroll
            for (int mt = 0; mt < 2; mt++)
                #pragma unroll
                for (int nt = 0; nt < 12; nt++)
                    mma16816(acc[mt][nt], ah[mt], &bl[nt >> 1][(nt & 1) * 2]);
        }
        __syncthreads();
    }

    // ---- C fragments -> smem (tiles region reused) ----
    #pragma unroll
    for (int mt = 0; mt < 2; mt++)
        #pragma unroll
        for (int nt = 0; nt < 12; nt++) {
            int row = wr * 32 + mt * 16 + (lane >> 2);
            int col = wc * 96 + nt * 8 + (lane & 3) * 2;
            *(float2*)&Cs[row * CS_LD + col]       = make_float2(acc[mt][nt][0], acc[mt][nt][1]);
            *(float2*)&Cs[(row + 8) * CS_LD + col] = make_float2(acc[mt][nt][2], acc[mt][nt][3]);
        }
    #pragma unroll
    for (int l = 0; l < 4; l++)
        atomicAdd(&rowsum[(tid >> 3) + 32 * l], ss[l]);
    __syncthreads();

    // ---- per-row softmax chain ----
    if (tid < 128) {
        const int    b  = b0 + tid;
        const float  s  = TAUF / fmaxf(sqrtf(rowsum[tid]), 1e-12f);
        const float* cr = Cs + tid * CS_LD;

        float L[9];
        #pragma unroll
        for (int d = 0; d < 9; d++) {
            float mx = -1e30f;
            #pragma unroll
            for (int m = 0; m < 10; m++) mx = fmaxf(mx, cr[d * 10 + m]);
            float se = 0.f, ac = 0.f;
            #pragma unroll
            for (int m = 0; m < 10; m++) {
                float e = expf(s * (cr[d * 10 + m] - mx));
                se += e;
                ac += e * cr[96 + d * 10 + m];
            }
            L[d] = s * ac / se;
        }
        float mx2 = -1e30f;
        #pragma unroll
        for (int d = 0; d < 9; d++) mx2 = fmaxf(mx2, L[d]);
        float ex[9], s2 = 0.f;
        #pragma unroll
        for (int d = 0; d < 9; d++) { ex[d] = expf(L[d] - mx2); s2 += ex[d]; }
        const float inv = 1.0f / s2;
        #pragma unroll
        for (int d = 0; d < 9; d++) out[b * 9 + d] = ex[d] * inv;
    }
}

// ----------------------------------------------------------------------------
extern "C" void kernel_launch(void* const* d_in, const int* in_sizes, int n_in,
                              void* d_out, int out_size)
{
    const float* feature = (const float*)d_in[0];  // (16384, 2048)
    const float* Wt      = (const float*)d_in[1];  // (768, 2048)
    const float* Wd      = (const float*)d_in[2];  // (768, 2048)
    const float* memtab  = (const float*)d_in[3];  // (9, 10, 768)
    const void*  cat     = d_in[4];                // (16384,) int32/int64

    cudaFuncSetAttribute(fused_kernel,
                         cudaFuncAttributeMaxDynamicSharedMemorySize, SMEM_TOT);

    dim3 gA(8, 16, 4);
    build_part_kernel<<<gA, 256>>>(Wt, Wd, memtab, cat);
    split_B_kernel<<<NROWS, 256>>>();
    fused_kernel<<<16384 / 128, 256, SMEM_TOT>>>(feature, (float*)d_out);
}